// round 2
// baseline (speedup 1.0000x reference)
#include <cuda_runtime.h>
#include <cfloat>
#include <cstdint>
#include <cstddef>

#define B_  65536
#define E_  384
#define H_  512
#define KC_ 256
#define Q_  4

// ---------------- scratch (static device globals; referenced directly from device code) ----------------
__device__ float g_scratch[(size_t)B_ * H_];   // enc hidden -> VQ scores -> dec hidden
__device__ float g_z[(size_t)B_ * H_];         // encoder output z
__device__ float g_res[(size_t)B_ * H_];       // running residual
__device__ float g_cbnorm[Q_ * KC_];           // ||cb_qk||^2
__device__ float g_commit_part[Q_ * (B_ / 8)];           // per-block commit partials
__device__ float g_recon_part[(B_ / 128) * (E_ / 128)];  // per-block recon partials

// which scratch buffer a GEMM reads/writes
enum Buf { BUF_EXT = 0, BUF_SCRATCH = 1, BUF_Z = 2, BUF_RES = 3 };

__device__ __forceinline__ float* buf_ptr(int b, const float* ext) {
    switch (b) {
        case BUF_SCRATCH: return g_scratch;
        case BUF_Z:       return g_z;
        case BUF_RES:     return g_res;
        default:          return (float*)ext;
    }
}

// ---------------- codebook norms: one warp per code ----------------
__global__ void cbnorm_kernel(const float* __restrict__ cb) {
    int warp = (blockIdx.x * blockDim.x + threadIdx.x) >> 5;
    int lane = threadIdx.x & 31;
    if (warp >= Q_ * KC_) return;
    const float* v = cb + (size_t)warp * H_;
    float s = 0.f;
    for (int i = lane; i < H_; i += 32) s = fmaf(v[i], v[i], s);
    #pragma unroll
    for (int o = 16; o; o >>= 1) s += __shfl_down_sync(0xffffffffu, s, o);
    if (lane == 0) g_cbnorm[warp] = s;
}

// ---------------- generic fp32 GEMM: C = act( (A - A2?) @ W(+T) + bias ) ----------------
// BM=BN=128, BK=8, 256 threads, 8x8 per thread.
// A is selected by ABUF (ext pointer or device global); C by CBUF. SUBA2 subtracts g_res from g_z.
template<bool RELU, bool TRANSB, bool LOSS, bool SUBA2, bool HASBIAS, int ABUF, int CBUF>
__global__ __launch_bounds__(256) void gemm_kernel(
    const float* __restrict__ Aext, const float* __restrict__ W,
    const float* __restrict__ bias, float* __restrict__ Cext,
    const float* __restrict__ Xc, int M, int N, int K)
{
    __shared__ float As[8][132];
    __shared__ float Ws[8][132];

    const float* A = buf_ptr(ABUF, Aext);
    float*       C = (CBUF == BUF_EXT) ? Cext : buf_ptr(CBUF, nullptr);

    const int tid = threadIdx.x;
    const int m0 = blockIdx.y * 128;
    const int n0 = blockIdx.x * 128;

    const int ar = tid >> 1;          // A tile row 0..127
    const int ac = (tid & 1) * 4;     // A tile k offset 0/4
    const int wr = tid >> 5;          // W (normal): k 0..7
    const int wc = (tid & 31) * 4;    // W (normal): n offset
    const int tr = tid >> 1;          // W (TRANSB): n 0..127
    const int tc = (tid & 1) * 4;     // W (TRANSB): k offset

    const int tx = tid & 15;
    const int ty = tid >> 4;

    float acc[8][8];
    #pragma unroll
    for (int i = 0; i < 8; i++)
        #pragma unroll
        for (int j = 0; j < 8; j++) acc[i][j] = 0.f;

    for (int k0 = 0; k0 < K; k0 += 8) {
        float4 av = *(const float4*)(A + (size_t)(m0 + ar) * K + k0 + ac);
        if (SUBA2) {
            float4 bv = *(const float4*)(g_res + (size_t)(m0 + ar) * K + k0 + ac);
            av.x -= bv.x; av.y -= bv.y; av.z -= bv.z; av.w -= bv.w;
        }
        As[ac + 0][ar] = av.x; As[ac + 1][ar] = av.y;
        As[ac + 2][ar] = av.z; As[ac + 3][ar] = av.w;

        if (TRANSB) {
            float4 wv = *(const float4*)(W + (size_t)(n0 + tr) * K + k0 + tc);
            Ws[tc + 0][tr] = wv.x; Ws[tc + 1][tr] = wv.y;
            Ws[tc + 2][tr] = wv.z; Ws[tc + 3][tr] = wv.w;
        } else {
            float4 wv = *(const float4*)(W + (size_t)(k0 + wr) * N + n0 + wc);
            *(float4*)&Ws[wr][wc] = wv;
        }
        __syncthreads();

        #pragma unroll
        for (int kk = 0; kk < 8; kk++) {
            float areg[8], breg[8];
            #pragma unroll
            for (int i = 0; i < 8; i++) areg[i] = As[kk][ty * 8 + i];
            #pragma unroll
            for (int j = 0; j < 8; j++) breg[j] = Ws[kk][tx * 8 + j];
            #pragma unroll
            for (int i = 0; i < 8; i++)
                #pragma unroll
                for (int j = 0; j < 8; j++)
                    acc[i][j] = fmaf(areg[i], breg[j], acc[i][j]);
        }
        __syncthreads();
    }

    float lsum = 0.f;
    #pragma unroll
    for (int i = 0; i < 8; i++) {
        const int row = m0 + ty * 8 + i;
        #pragma unroll
        for (int j = 0; j < 8; j++) {
            const int col = n0 + tx * 8 + j;
            float v = acc[i][j];
            if (HASBIAS) v += __ldg(bias + col);
            if (RELU) v = fmaxf(v, 0.f);
            C[(size_t)row * N + col] = v;
            if (LOSS) {
                float d = v - __ldg(Xc + (size_t)row * N + col);
                lsum = fmaf(d, d, lsum);
            }
        }
    }
    if (LOSS) {
        #pragma unroll
        for (int o = 16; o; o >>= 1) lsum += __shfl_down_sync(0xffffffffu, lsum, o);
        __shared__ float red[8];
        if ((tid & 31) == 0) red[tid >> 5] = lsum;
        __syncthreads();
        if (tid == 0) {
            float t = 0.f;
            #pragma unroll
            for (int i = 0; i < 8; i++) t += red[i];
            g_recon_part[blockIdx.y * gridDim.x + blockIdx.x] = t;
        }
    }
}

// ---------------- residual = z (copy) ----------------
__global__ void copy_kernel() {
    size_t n4 = (size_t)B_ * H_ / 4;
    size_t i = (size_t)blockIdx.x * blockDim.x + threadIdx.x;
    size_t stride = (size_t)gridDim.x * blockDim.x;
    const float4* s = (const float4*)g_z;
    float4* d = (float4*)g_res;
    for (; i < n4; i += stride) d[i] = s[i];
}

// ---------------- per-level argmin + residual update + commit partial ----------------
// 256 threads = 8 warps = 8 rows per block. Reference-exact earliest-min tie-break.
__global__ __launch_bounds__(256) void argmin_update_kernel(
    int q, const float* __restrict__ cb, float* __restrict__ idx_out, int write_idx)
{
    const int warp = threadIdx.x >> 5;
    const int lane = threadIdx.x & 31;
    const int row = blockIdx.x * 8 + warp;

    const float* srow = g_scratch + (size_t)row * KC_;
    float best = FLT_MAX;
    int bidx = KC_;
    #pragma unroll
    for (int k0 = 0; k0 < KC_; k0 += 32) {
        int k = k0 + lane;
        float d = g_cbnorm[q * KC_ + k] - 2.0f * srow[k];
        if (d < best) { best = d; bidx = k; }   // strict '<' keeps earliest k per lane
    }
    #pragma unroll
    for (int o = 16; o; o >>= 1) {
        float ob = __shfl_down_sync(0xffffffffu, best, o);
        int   oi = __shfl_down_sync(0xffffffffu, bidx, o);
        if (ob < best || (ob == best && oi < bidx)) { best = ob; bidx = oi; }
    }
    bidx = __shfl_sync(0xffffffffu, bidx, 0);

    if (write_idx && lane == 0)
        idx_out[(size_t)row * Q_ + q] = (float)bidx;

    const float* cv = cb + ((size_t)q * KC_ + bidx) * H_;
    float* rrow = g_res + (size_t)row * H_;
    float cs = 0.f;
    #pragma unroll
    for (int p = lane * 4; p < H_; p += 128) {
        float4 r = *(const float4*)(rrow + p);
        float4 c = *(const float4*)(cv + p);
        r.x -= c.x; r.y -= c.y; r.z -= c.z; r.w -= c.w;
        *(float4*)(rrow + p) = r;
        cs += r.x * r.x + r.y * r.y + r.z * r.z + r.w * r.w;
    }
    #pragma unroll
    for (int o = 16; o; o >>= 1) cs += __shfl_down_sync(0xffffffffu, cs, o);

    __shared__ float wsum[8];
    if (lane == 0) wsum[warp] = cs;
    __syncthreads();
    if (threadIdx.x == 0) {
        float t = 0.f;
        #pragma unroll
        for (int i = 0; i < 8; i++) t += wsum[i];
        g_commit_part[(size_t)q * (B_ / 8) + blockIdx.x] = t;
    }
}

// ---------------- final scalar reduction ----------------
__global__ void finalize_kernel(float* __restrict__ out) {
    __shared__ double sc[256], sr[256];
    double c = 0.0, r = 0.0;
    for (int i = threadIdx.x; i < Q_ * (B_ / 8); i += 256) c += (double)g_commit_part[i];
    for (int i = threadIdx.x; i < (B_ / 128) * (E_ / 128); i += 256) r += (double)g_recon_part[i];
    sc[threadIdx.x] = c; sr[threadIdx.x] = r;
    __syncthreads();
    for (int s = 128; s; s >>= 1) {
        if (threadIdx.x < s) { sc[threadIdx.x] += sc[threadIdx.x + s]; sr[threadIdx.x] += sr[threadIdx.x + s]; }
        __syncthreads();
    }
    if (threadIdx.x == 0) {
        out[(size_t)B_ * E_ + (size_t)B_ * Q_ + 0] = (float)(sr[0] / ((double)B_ * (double)E_));
        out[(size_t)B_ * E_ + (size_t)B_ * Q_ + 1] = (float)(0.25 * sc[0] / ((double)B_ * (double)H_));
    }
}

// ---------------- launch: kernel launches ONLY ----------------
extern "C" void kernel_launch(void* const* d_in, const int* in_sizes, int n_in,
                              void* d_out, int out_size) {
    const float* x   = (const float*)d_in[0];
    const float* We1 = (const float*)d_in[1];
    const float* be1 = (const float*)d_in[2];
    const float* We2 = (const float*)d_in[3];
    const float* be2 = (const float*)d_in[4];
    const float* Wd1 = (const float*)d_in[5];
    const float* bd1 = (const float*)d_in[6];
    const float* Wd2 = (const float*)d_in[7];
    const float* bd2 = (const float*)d_in[8];
    const float* cb  = (const float*)d_in[9];
    float* out = (float*)d_out;

    // Output layout assumption: [reconstructed (B*E) | indices-as-float (B*Q) | recon_loss | commit_loss]
    const int full = out_size >= (int)((size_t)B_ * E_ + (size_t)B_ * Q_ + 2);
    float* idx_out = out + (size_t)B_ * E_;

    dim3 blk(256);

    cbnorm_kernel<<<(Q_ * KC_) / 8, 256>>>(cb);

    // enc1: scratch = relu(x @ We1 + be1)      [B,384]x[384,512]
    gemm_kernel<true,  false, false, false, true,  BUF_EXT,     BUF_SCRATCH>
        <<<dim3(H_ / 128, B_ / 128), blk>>>(x, We1, be1, nullptr, nullptr, B_, H_, E_);
    // enc2: z = scratch @ We2 + be2            [B,512]x[512,512]
    gemm_kernel<false, false, false, false, true,  BUF_SCRATCH, BUF_Z>
        <<<dim3(H_ / 128, B_ / 128), blk>>>(nullptr, We2, be2, nullptr, nullptr, B_, H_, H_);

    // residual = z
    copy_kernel<<<2048, 256>>>();

    // residual VQ: 4 levels of (scores GEMM -> argmin + residual update)
    for (int q = 0; q < Q_; q++) {
        gemm_kernel<false, true, false, false, false, BUF_RES, BUF_SCRATCH>
            <<<dim3(KC_ / 128, B_ / 128), blk>>>(nullptr, cb + (size_t)q * KC_ * H_,
                                                 nullptr, nullptr, nullptr, B_, KC_, H_);
        argmin_update_kernel<<<B_ / 8, 256>>>(q, cb, idx_out, full);
    }

    // dec1: scratch = relu((z - res) @ Wd1 + bd1)   (quantized = z - residual_final)
    gemm_kernel<true,  false, false, true,  true,  BUF_Z,       BUF_SCRATCH>
        <<<dim3(H_ / 128, B_ / 128), blk>>>(nullptr, Wd1, bd1, nullptr, nullptr, B_, H_, H_);
    // dec2: out = scratch @ Wd2 + bd2, fused recon-loss partials vs x
    gemm_kernel<false, false, true,  false, true,  BUF_SCRATCH, BUF_EXT>
        <<<dim3(E_ / 128, B_ / 128), blk>>>(nullptr, Wd2, bd2, out, x, B_, E_, H_);

    if (full) finalize_kernel<<<1, 256>>>(out);
}